// round 2
// baseline (speedup 1.0000x reference)
#include <cuda_runtime.h>
#include <math.h>

// Problem constants (match setup_inputs)
#define N0C 50000
#define E0C 800000
#define N1C 10000
#define E1C 160000
#define FC  128
#define HC  256
#define BC  64

// ---------------- static scratch (no allocations allowed) ----------------
__device__ float g_xw [N0C * HC];
__device__ float g_x1 [N0C * HC];
__device__ float g_x2 [N0C * HC];
__device__ float g_h  [N0C * HC];
__device__ float g_dinv0[N0C];

__device__ float g_h1cat[N1C * 2 * HC];
__device__ float g_yw [N1C * HC];
__device__ float g_y1 [N1C * HC];
__device__ float g_y2 [N1C * HC];
__device__ float g_hb [N1C * HC];
__device__ float g_dinv1[N1C];

__device__ float g_z [BC * 4 * HC];

// ---------------- small utility kernels ----------------
__global__ void fill_kernel(float* p, int n, float v) {
    int i = blockIdx.x * blockDim.x + threadIdx.x;
    if (i < n) p[i] = v;
}

__global__ void deg_accum_kernel(const int* __restrict__ col,
                                 const float* __restrict__ ew,
                                 float* __restrict__ deg, int E) {
    int e = blockIdx.x * blockDim.x + threadIdx.x;
    if (e < E) atomicAdd(&deg[col[e]], ew[e]);
}

__global__ void finalize_dinv_kernel(float* deg, int n) {
    int i = blockIdx.x * blockDim.x + threadIdx.x;
    if (i < n) {
        float d = deg[i];
        deg[i] = (d > 0.f) ? rsqrtf(d) : 0.f;
    }
}

// out[i,f] = bias[f] + dinv[i]^2 * xw[i,f]   (self-loop term + bias)
__global__ void self_init_kernel(float* __restrict__ out,
                                 const float* __restrict__ xw,
                                 const float* __restrict__ dinv,
                                 const float* __restrict__ bias,
                                 int M, int F) {
    int i = blockIdx.x * blockDim.x + threadIdx.x;
    if (i >= M * F) return;
    int m = i / F;
    int f = i - m * F;
    float di = dinv[m];
    out[i] = bias[f] + di * di * xw[i];
}

// out[col, :] += (dinv[row]*ew*dinv[col]) * xw[row, :]   (F = 256, float4 lanes)
__global__ void gcn_scatter_v4(const float* __restrict__ xw,
                               const int* __restrict__ row,
                               const int* __restrict__ col,
                               const float* __restrict__ ew,
                               const float* __restrict__ dinv,
                               float* __restrict__ out,
                               int E, int edgesPerBlock) {
    int f4 = threadIdx.x & 63;   // 64 float4 lanes = 256 floats
    int es = threadIdx.x >> 6;   // 4 edge slots
    int e0 = blockIdx.x * edgesPerBlock;
    int e1 = e0 + edgesPerBlock;
    if (e1 > E) e1 = E;
    for (int e = e0 + es; e < e1; e += 4) {
        int r = row[e], c = col[e];
        float coef = dinv[r] * ew[e] * dinv[c];
        float4 v = *reinterpret_cast<const float4*>(xw + (size_t)r * HC + f4 * 4);
        float* dst = out + (size_t)c * HC + f4 * 4;
        atomicAdd(dst + 0, coef * v.x);
        atomicAdd(dst + 1, coef * v.y);
        atomicAdd(dst + 2, coef * v.z);
        atomicAdd(dst + 3, coef * v.w);
    }
}

// ---------------- 128x128x16 double-buffered SGEMM ----------------
// C = act( [A1|A2] @ W + bias ).  A1: MxK1, A2: Mx(K-K1), row-major. W: KxN.
// K, K1 multiples of 16. N multiple of 128. reluIn on A loads, reluOut+bias on C.
#define TBM 128
#define TBN 128
#define TBK 16
#define ASTRIDE (TBM + 4)

__global__ __launch_bounds__(256, 2)
void gemm128_kernel(const float* __restrict__ A1,
                    const float* __restrict__ A2,
                    int K1, int K,
                    const float* __restrict__ W,
                    const float* __restrict__ bias,
                    float* __restrict__ C,
                    int M, int N,
                    int reluIn, int reluOut) {
    __shared__ __align__(16) float As[2][TBK][ASTRIDE];
    __shared__ __align__(16) float Ws[2][TBK][TBN];

    const int bm = blockIdx.y * TBM;
    const int bn = blockIdx.x * TBN;
    const int tid = threadIdx.x;            // 0..255
    const int tx = tid & 15;                // N dir (8 cols each)
    const int ty = tid >> 4;                // M dir (8 rows each)
    const int K2 = K - K1;

    // A-load mapping: idx in [0,512): row = idx>>2, kq = idx&3 (float4 along K)
    const int arow0 = tid >> 2;
    const int akq   = tid & 3;
    // W-load mapping: idx in [0,512): k = idx>>5, n4 = idx&31 (float4 along N)
    const int wk0 = tid >> 5;
    const int wn4 = tid & 31;

    float acc[8][8];
#pragma unroll
    for (int i = 0; i < 8; i++)
#pragma unroll
        for (int j = 0; j < 8; j++) acc[i][j] = 0.f;

    const int nt = K / TBK;

    float4 pa[2], pw[2];

    // ---- load tile 0 ----
    {
        const int gk0 = 0;
#pragma unroll
        for (int i = 0; i < 2; i++) {
            int row = arow0 + i * 64;
            int gm = bm + row;
            float4 v = make_float4(0.f, 0.f, 0.f, 0.f);
            if (gm < M) {
                const float* src = (gk0 < K1) ? (A1 + (size_t)gm * K1 + gk0)
                                              : (A2 + (size_t)gm * K2 + (gk0 - K1));
                v = *reinterpret_cast<const float4*>(src + akq * 4);
            }
            if (reluIn) {
                v.x = fmaxf(v.x, 0.f); v.y = fmaxf(v.y, 0.f);
                v.z = fmaxf(v.z, 0.f); v.w = fmaxf(v.w, 0.f);
            }
            As[0][akq * 4 + 0][row] = v.x;
            As[0][akq * 4 + 1][row] = v.y;
            As[0][akq * 4 + 2][row] = v.z;
            As[0][akq * 4 + 3][row] = v.w;
        }
#pragma unroll
        for (int i = 0; i < 2; i++) {
            int k = wk0 + i * 8;
            float4 v = *reinterpret_cast<const float4*>(W + (size_t)(gk0 + k) * N + bn + wn4 * 4);
            *reinterpret_cast<float4*>(&Ws[0][k][wn4 * 4]) = v;
        }
    }
    __syncthreads();

    int cur = 0;
    for (int t = 0; t < nt; t++) {
        // prefetch next tile into registers
        if (t + 1 < nt) {
            const int gk0 = (t + 1) * TBK;
#pragma unroll
            for (int i = 0; i < 2; i++) {
                int row = arow0 + i * 64;
                int gm = bm + row;
                float4 v = make_float4(0.f, 0.f, 0.f, 0.f);
                if (gm < M) {
                    const float* src = (gk0 < K1) ? (A1 + (size_t)gm * K1 + gk0)
                                                  : (A2 + (size_t)gm * K2 + (gk0 - K1));
                    v = *reinterpret_cast<const float4*>(src + akq * 4);
                }
                if (reluIn) {
                    v.x = fmaxf(v.x, 0.f); v.y = fmaxf(v.y, 0.f);
                    v.z = fmaxf(v.z, 0.f); v.w = fmaxf(v.w, 0.f);
                }
                pa[i] = v;
            }
#pragma unroll
            for (int i = 0; i < 2; i++) {
                int k = wk0 + i * 8;
                pw[i] = *reinterpret_cast<const float4*>(W + (size_t)(gk0 + k) * N + bn + wn4 * 4);
            }
        }

        // compute current tile
#pragma unroll
        for (int k = 0; k < TBK; k++) {
            float a[8], w[8];
            float4 a0 = *reinterpret_cast<const float4*>(&As[cur][k][ty * 8]);
            float4 a1 = *reinterpret_cast<const float4*>(&As[cur][k][ty * 8 + 4]);
            float4 w0 = *reinterpret_cast<const float4*>(&Ws[cur][k][tx * 8]);
            float4 w1 = *reinterpret_cast<const float4*>(&Ws[cur][k][tx * 8 + 4]);
            a[0] = a0.x; a[1] = a0.y; a[2] = a0.z; a[3] = a0.w;
            a[4] = a1.x; a[5] = a1.y; a[6] = a1.z; a[7] = a1.w;
            w[0] = w0.x; w[1] = w0.y; w[2] = w0.z; w[3] = w0.w;
            w[4] = w1.x; w[5] = w1.y; w[6] = w1.z; w[7] = w1.w;
#pragma unroll
            for (int i = 0; i < 8; i++)
#pragma unroll
                for (int j = 0; j < 8; j++)
                    acc[i][j] += a[i] * w[j];
        }

        // stage prefetched regs into the other buffer
        if (t + 1 < nt) {
            int nxt = cur ^ 1;
#pragma unroll
            for (int i = 0; i < 2; i++) {
                int row = arow0 + i * 64;
                As[nxt][akq * 4 + 0][row] = pa[i].x;
                As[nxt][akq * 4 + 1][row] = pa[i].y;
                As[nxt][akq * 4 + 2][row] = pa[i].z;
                As[nxt][akq * 4 + 3][row] = pa[i].w;
            }
#pragma unroll
            for (int i = 0; i < 2; i++) {
                int k = wk0 + i * 8;
                *reinterpret_cast<float4*>(&Ws[nxt][k][wn4 * 4]) = pw[i];
            }
            __syncthreads();
            cur = nxt;
        }
    }

    // epilogue
#pragma unroll
    for (int i = 0; i < 8; i++) {
        int gm = bm + ty * 8 + i;
        if (gm >= M) continue;
        float* crow = C + (size_t)gm * N + bn + tx * 8;
#pragma unroll
        for (int jj = 0; jj < 2; jj++) {
            float4 v;
            float* a4 = &acc[i][jj * 4];
            v.x = a4[0]; v.y = a4[1]; v.z = a4[2]; v.w = a4[3];
            if (bias) {
                const float* b4 = bias + bn + tx * 8 + jj * 4;
                v.x += b4[0]; v.y += b4[1]; v.z += b4[2]; v.w += b4[3];
            }
            if (reluOut) {
                v.x = fmaxf(v.x, 0.f); v.y = fmaxf(v.y, 0.f);
                v.z = fmaxf(v.z, 0.f); v.w = fmaxf(v.w, 0.f);
            }
            *reinterpret_cast<float4*>(crow + jj * 4) = v;
        }
    }
}

// ---------------- segment pool (sum + max), values >= 0 -----------
__global__ void segpool_kernel(const float* __restrict__ in,
                               const int* __restrict__ gatherIdx,
                               const int* __restrict__ seg,
                               int M, int F,
                               float* __restrict__ outSum,
                               float* __restrict__ outMax,
                               int ldOut, int nodesPerBlock) {
    int f = threadIdx.x;
    int n0 = blockIdx.x * nodesPerBlock;
    int n1 = n0 + nodesPerBlock;
    if (n1 > M) n1 = M;
    if (n0 >= n1) return;
    int cur = seg[n0];
    float s = 0.f, mx = 0.f;
    for (int n = n0; n < n1; n++) {
        int sg = seg[n];
        if (sg != cur) {
            atomicAdd(&outSum[cur * ldOut + f], s);
            atomicMax((int*)&outMax[cur * ldOut + f], __float_as_int(mx));
            s = 0.f; mx = 0.f; cur = sg;
        }
        int rowi = gatherIdx ? gatherIdx[n] : n;
        float v = in[(size_t)rowi * F + f];
        s += v;
        mx = fmaxf(mx, v);
    }
    atomicAdd(&outSum[cur * ldOut + f], s);
    atomicMax((int*)&outMax[cur * ldOut + f], __float_as_int(mx));
}

// ---------------- head: BN -> lin1+relu -> lin2 -> softmax ---------------
__global__ void head_kernel(const float* __restrict__ z,
                            const float* __restrict__ gamma,
                            const float* __restrict__ beta,
                            const float* __restrict__ mean,
                            const float* __restrict__ var,
                            const float* __restrict__ W1,
                            const float* __restrict__ b1,
                            const float* __restrict__ W2,
                            const float* __restrict__ b2,
                            float* __restrict__ out) {
    __shared__ float zn[4 * HC];
    __shared__ float s1[HC];
    __shared__ float logits[16];
    int b = blockIdx.x;
    int t = threadIdx.x;
    for (int k = t; k < 4 * HC; k += 256) {
        float v = z[b * 4 * HC + k];
        zn[k] = (v - mean[k]) * rsqrtf(var[k] + 1e-5f) * gamma[k] + beta[k];
    }
    __syncthreads();
    float acc = b1[t];
    for (int k = 0; k < 4 * HC; k++) acc += zn[k] * W1[k * HC + t];
    s1[t] = fmaxf(acc, 0.f);
    __syncthreads();
    if (t < 10) {
        float a2 = b2[t];
        for (int k = 0; k < HC; k++) a2 += s1[k] * W2[k * 10 + t];
        logits[t] = a2;
    }
    __syncthreads();
    if (t == 0) {
        float mx = logits[0];
        for (int c = 1; c < 10; c++) mx = fmaxf(mx, logits[c]);
        float e[10], sum = 0.f;
        for (int c = 0; c < 10; c++) { e[c] = expf(logits[c] - mx); sum += e[c]; }
        float inv = 1.f / sum;
        for (int c = 0; c < 10; c++) out[b * 10 + c] = e[c] * inv;
    }
}

// ---------------- orchestration ----------------
static inline int ceil_div(int a, int b) { return (a + b - 1) / b; }

extern "C" void kernel_launch(void* const* d_in, const int* in_sizes, int n_in,
                              void* d_out, int out_size) {
    const float* x      = (const float*)d_in[0];
    const int*   ei0    = (const int*)d_in[1];
    const float* ew0    = (const float*)d_in[2];
    const int*   batch0 = (const int*)d_in[3];
    const int*   cover  = (const int*)d_in[4];
    const int*   ei1    = (const int*)d_in[5];
    const float* ew1    = (const float*)d_in[6];
    const int*   batch1 = (const int*)d_in[7];
    const float* W_in0  = (const float*)d_in[8];
    const float* b_in0  = (const float*)d_in[9];
    const float* W_in1  = (const float*)d_in[10];
    const float* b_in1  = (const float*)d_in[11];
    const float* W_jk_in= (const float*)d_in[12];
    const float* b_jk_in= (const float*)d_in[13];
    const float* W_b0   = (const float*)d_in[14];
    const float* b_b0   = (const float*)d_in[15];
    const float* W_b1   = (const float*)d_in[16];
    const float* b_b1   = (const float*)d_in[17];
    const float* W_jk_b = (const float*)d_in[18];
    const float* b_jk_b = (const float*)d_in[19];
    const float* bn_g   = (const float*)d_in[20];
    const float* bn_b   = (const float*)d_in[21];
    const float* bn_m   = (const float*)d_in[22];
    const float* bn_v   = (const float*)d_in[23];
    const float* W_lin1 = (const float*)d_in[24];
    const float* b_lin1 = (const float*)d_in[25];
    const float* W_lin2 = (const float*)d_in[26];
    const float* b_lin2 = (const float*)d_in[27];
    float* out = (float*)d_out;

    const int N0 = in_sizes[3];
    const int E0 = in_sizes[2];
    const int N1 = in_sizes[7];
    const int E1 = in_sizes[6];
    const int H = HC;

    const int* row0 = ei0;
    const int* col0 = ei0 + E0;
    const int* nodeC = cover;
    const int* clusC = cover + N0;
    const int* row1 = ei1;
    const int* col1 = ei1 + E1;

    float *xw, *x1, *x2, *h, *dinv0, *h1cat, *yw, *y1, *y2, *hb, *dinv1, *z;
    cudaGetSymbolAddress((void**)&xw, g_xw);
    cudaGetSymbolAddress((void**)&x1, g_x1);
    cudaGetSymbolAddress((void**)&x2, g_x2);
    cudaGetSymbolAddress((void**)&h,  g_h);
    cudaGetSymbolAddress((void**)&dinv0, g_dinv0);
    cudaGetSymbolAddress((void**)&h1cat, g_h1cat);
    cudaGetSymbolAddress((void**)&yw, g_yw);
    cudaGetSymbolAddress((void**)&y1, g_y1);
    cudaGetSymbolAddress((void**)&y2, g_y2);
    cudaGetSymbolAddress((void**)&hb, g_hb);
    cudaGetSymbolAddress((void**)&dinv1, g_dinv1);
    cudaGetSymbolAddress((void**)&z,  g_z);

    dim3 gemmBlk(256);
    dim3 g0(H / TBN, ceil_div(N0, TBM));
    dim3 g1(H / TBN, ceil_div(N1, TBM));

    // Launches 1-5 (small setup) so the 6th launch -- profiled by ncu -s 5 -c 1 --
    // is the first big GEMM.
    fill_kernel<<<ceil_div(N0, 256), 256>>>(dinv0, N0, 1.f);                 // 1
    deg_accum_kernel<<<ceil_div(E0, 256), 256>>>(col0, ew0, dinv0, E0);      // 2
    finalize_dinv_kernel<<<ceil_div(N0, 256), 256>>>(dinv0, N0);             // 3
    fill_kernel<<<ceil_div(BC * 4 * H, 256), 256>>>(z, BC * 4 * H, 0.f);     // 4
    fill_kernel<<<ceil_div(N1 * 2 * H, 256), 256>>>(h1cat, N1 * 2 * H, 0.f); // 5

    // ---- level 0: GCN 1 ----
    gemm128_kernel<<<g0, gemmBlk>>>(x, x, FC, FC, W_in0, NULL, xw, N0, H, 0, 0);  // 6 (profiled)
    self_init_kernel<<<ceil_div(N0 * H, 256), 256>>>(x1, xw, dinv0, b_in0, N0, H);
    gcn_scatter_v4<<<ceil_div(E0, 16), 256>>>(xw, row0, col0, ew0, dinv0, x1, E0, 16);

    // level-1 dinv (independent, interleaved here)
    fill_kernel<<<ceil_div(N1, 256), 256>>>(dinv1, N1, 1.f);
    deg_accum_kernel<<<ceil_div(E1, 256), 256>>>(col1, ew1, dinv1, E1);
    finalize_dinv_kernel<<<ceil_div(N1, 256), 256>>>(dinv1, N1);

    // ---- level 0: GCN 2 ----
    gemm128_kernel<<<g0, gemmBlk>>>(x1, x1, H, H, W_in1, NULL, xw, N0, H, 1, 0);
    self_init_kernel<<<ceil_div(N0 * H, 256), 256>>>(x2, xw, dinv0, b_in1, N0, H);
    gcn_scatter_v4<<<ceil_div(E0, 16), 256>>>(xw, row0, col0, ew0, dinv0, x2, E0, 16);

    // ---- level 0: JK cat + linear + relu ----
    gemm128_kernel<<<g0, gemmBlk>>>(x1, x2, H, 2 * H, W_jk_in, b_jk_in, h, N0, H, 1, 1);

    // ---- pools ----
    segpool_kernel<<<ceil_div(N0, 128), 256>>>(h, NULL, batch0, N0, H,
                                               z + 0, z + H, 4 * H, 128);
    segpool_kernel<<<ceil_div(N0, 128), 256>>>(h, nodeC, clusC, N0, H,
                                               h1cat + 0, h1cat + H, 2 * H, 128);

    // ---- level 1: GCN 1 ----
    gemm128_kernel<<<g1, gemmBlk>>>(h1cat, h1cat, 2 * H, 2 * H, W_b0, NULL, yw, N1, H, 0, 0);
    self_init_kernel<<<ceil_div(N1 * H, 256), 256>>>(y1, yw, dinv1, b_b0, N1, H);
    gcn_scatter_v4<<<ceil_div(E1, 16), 256>>>(yw, row1, col1, ew1, dinv1, y1, E1, 16);

    // ---- level 1: GCN 2 ----
    gemm128_kernel<<<g1, gemmBlk>>>(y1, y1, H, H, W_b1, NULL, yw, N1, H, 1, 0);
    self_init_kernel<<<ceil_div(N1 * H, 256), 256>>>(y2, yw, dinv1, b_b1, N1, H);
    gcn_scatter_v4<<<ceil_div(E1, 16), 256>>>(yw, row1, col1, ew1, dinv1, y2, E1, 16);

    // ---- level 1: JK ----
    gemm128_kernel<<<g1, gemmBlk>>>(y1, y2, H, 2 * H, W_jk_b, b_jk_b, hb, N1, H, 1, 1);

    // ---- level-1 batch pool ----
    segpool_kernel<<<ceil_div(N1, 128), 256>>>(hb, NULL, batch1, N1, H,
                                               z + 2 * H, z + 3 * H, 4 * H, 128);

    // ---- head ----
    head_kernel<<<BC, 256>>>(z, bn_g, bn_b, bn_m, bn_v,
                             W_lin1, b_lin1, W_lin2, b_lin2, out);
}

// round 3
// speedup vs baseline: 1.2745x; 1.2745x over previous
#include <cuda_runtime.h>
#include <math.h>

#define N0C 50000
#define E0C 800000
#define N1C 10000
#define E1C 160000
#define FC  128
#define HC  256
#define BC  64

// ---------------- static scratch ----------------
__device__ float g_xw [N0C * HC];
__device__ float g_x1 [N0C * HC];
__device__ float g_x2 [N0C * HC];
__device__ float g_h  [N0C * HC];
__device__ float g_dinv0[N0C];

__device__ float g_h1cat[N1C * 2 * HC];
__device__ float g_yw [N1C * HC];
__device__ float g_y1 [N1C * HC];
__device__ float g_y2 [N1C * HC];
__device__ float g_hb [N1C * HC];
__device__ float g_dinv1[N1C];

__device__ float g_z [BC * 4 * HC];

// ---------------- utility kernels ----------------
__global__ void fill_kernel(float* p, int n, float v) {
    int i = blockIdx.x * blockDim.x + threadIdx.x;
    if (i < n) p[i] = v;
}

__global__ void deg_accum_kernel(const int* __restrict__ col,
                                 const float* __restrict__ ew,
                                 float* __restrict__ deg, int E) {
    int e = blockIdx.x * blockDim.x + threadIdx.x;
    if (e < E) atomicAdd(&deg[col[e]], ew[e]);
}

__global__ void finalize_dinv_kernel(float* deg, int n) {
    int i = blockIdx.x * blockDim.x + threadIdx.x;
    if (i < n) {
        float d = deg[i];
        deg[i] = (d > 0.f) ? rsqrtf(d) : 0.f;
    }
}

__global__ void self_init_kernel(float* __restrict__ out,
                                 const float* __restrict__ xw,
                                 const float* __restrict__ dinv,
                                 const float* __restrict__ bias,
                                 int M, int F) {
    int i = blockIdx.x * blockDim.x + threadIdx.x;
    if (i >= M * F) return;
    int m = i / F;
    int f = i - m * F;
    float di = dinv[m];
    out[i] = bias[f] + di * di * xw[i];
}

// R1-proven scatter: 256 threads = one edge's 256 features; 8 edges per block.
__global__ void gcn_scatter_kernel(const float* __restrict__ xw,
                                   const int* __restrict__ row,
                                   const int* __restrict__ col,
                                   const float* __restrict__ ew,
                                   const float* __restrict__ dinv,
                                   float* __restrict__ out,
                                   int E, int F, int edgesPerBlock) {
    int f = threadIdx.x;
    int e0 = blockIdx.x * edgesPerBlock;
    int e1 = e0 + edgesPerBlock;
    if (e1 > E) e1 = E;
    for (int e = e0; e < e1; e++) {
        int r = row[e], c = col[e];
        float coef = dinv[r] * ew[e] * dinv[c];
        atomicAdd(&out[c * F + f], coef * xw[r * F + f]);
    }
}

// ---------------- 128x128 BK=8 double-buffered SGEMM ----------------
// C = act( [A1|A2] @ W + bias ).  A1: MxK1, A2: Mx(K-K1) row-major. W: KxN.
// K, K1 multiples of 8 and K1 a multiple of 8 (here 128/256). N multiple of 128.
#define TBM 128
#define TBN 128
#define TBK 8

__global__ __launch_bounds__(256)
void gemm128_kernel(const float* __restrict__ A1,
                    const float* __restrict__ A2,
                    int K1, int K,
                    const float* __restrict__ W,
                    const float* __restrict__ bias,
                    float* __restrict__ C,
                    int M, int N,
                    int reluIn, int reluOut) {
    __shared__ __align__(16) float As[2][TBK][TBM];
    __shared__ __align__(16) float Ws[2][TBK][TBN];

    const int bm = blockIdx.y * TBM;
    const int bn = blockIdx.x * TBN;
    const int tid = threadIdx.x;
    const int tx = tid & 15;       // N dir
    const int ty = tid >> 4;       // M dir
    const int K2 = K - K1;

    // A loader: row = tid>>1 (0..127), kq = tid&1 -> k offsets kq*4..kq*4+3
    const int arow = tid >> 1;
    const int akq  = tid & 1;
    // W loader: k = tid>>5 (0..7), n4 = tid&31 -> float4 at col n4*4
    const int wk  = tid >> 5;
    const int wn4 = tid & 31;

    float acc[8][8];
#pragma unroll
    for (int i = 0; i < 8; i++)
#pragma unroll
        for (int j = 0; j < 8; j++) acc[i][j] = 0.f;

    const int nt = K / TBK;

    // ---- load tile 0 ----
    {
        int gm = bm + arow;
        float4 va = make_float4(0.f, 0.f, 0.f, 0.f);
        if (gm < M) {
            const float* src = (0 < K1) ? (A1 + (size_t)gm * K1) : (A2 + (size_t)gm * K2 - K1);
            va = *reinterpret_cast<const float4*>(src + akq * 4);
        }
        if (reluIn) {
            va.x = fmaxf(va.x, 0.f); va.y = fmaxf(va.y, 0.f);
            va.z = fmaxf(va.z, 0.f); va.w = fmaxf(va.w, 0.f);
        }
        As[0][akq * 4 + 0][arow] = va.x;
        As[0][akq * 4 + 1][arow] = va.y;
        As[0][akq * 4 + 2][arow] = va.z;
        As[0][akq * 4 + 3][arow] = va.w;
        float4 vw = *reinterpret_cast<const float4*>(W + (size_t)wk * N + bn + wn4 * 4);
        *reinterpret_cast<float4*>(&Ws[0][wk][wn4 * 4]) = vw;
    }
    __syncthreads();

    int cur = 0;
    for (int t = 0; t < nt; t++) {
        float4 pa, pw;
        const bool more = (t + 1 < nt);
        if (more) {
            const int gk0 = (t + 1) * TBK;
            int gm = bm + arow;
            pa = make_float4(0.f, 0.f, 0.f, 0.f);
            if (gm < M) {
                const float* src = (gk0 < K1) ? (A1 + (size_t)gm * K1 + gk0)
                                              : (A2 + (size_t)gm * K2 + (gk0 - K1));
                pa = *reinterpret_cast<const float4*>(src + akq * 4);
            }
            if (reluIn) {
                pa.x = fmaxf(pa.x, 0.f); pa.y = fmaxf(pa.y, 0.f);
                pa.z = fmaxf(pa.z, 0.f); pa.w = fmaxf(pa.w, 0.f);
            }
            pw = *reinterpret_cast<const float4*>(W + (size_t)(gk0 + wk) * N + bn + wn4 * 4);
        }

#pragma unroll
        for (int k = 0; k < TBK; k++) {
            float4 a0 = *reinterpret_cast<const float4*>(&As[cur][k][ty * 4]);
            float4 a1 = *reinterpret_cast<const float4*>(&As[cur][k][64 + ty * 4]);
            float4 w0 = *reinterpret_cast<const float4*>(&Ws[cur][k][tx * 4]);
            float4 w1 = *reinterpret_cast<const float4*>(&Ws[cur][k][64 + tx * 4]);
            float a[8] = {a0.x, a0.y, a0.z, a0.w, a1.x, a1.y, a1.z, a1.w};
            float w[8] = {w0.x, w0.y, w0.z, w0.w, w1.x, w1.y, w1.z, w1.w};
#pragma unroll
            for (int i = 0; i < 8; i++)
#pragma unroll
                for (int j = 0; j < 8; j++)
                    acc[i][j] += a[i] * w[j];
        }

        if (more) {
            int nxt = cur ^ 1;
            As[nxt][akq * 4 + 0][arow] = pa.x;
            As[nxt][akq * 4 + 1][arow] = pa.y;
            As[nxt][akq * 4 + 2][arow] = pa.z;
            As[nxt][akq * 4 + 3][arow] = pa.w;
            *reinterpret_cast<float4*>(&Ws[nxt][wk][wn4 * 4]) = pw;
            __syncthreads();
            cur = nxt;
        }
    }

    // epilogue: rows {bm+ty*4+i, bm+64+ty*4+i}, cols {bn+tx*4, bn+64+tx*4}
#pragma unroll
    for (int g = 0; g < 2; g++) {
#pragma unroll
        for (int i = 0; i < 4; i++) {
            int gm = bm + g * 64 + ty * 4 + i;
            if (gm >= M) continue;
            int ai = g * 4 + i;
#pragma unroll
            for (int jj = 0; jj < 2; jj++) {
                int gn = bn + jj * 64 + tx * 4;
                float4 v;
                v.x = acc[ai][jj * 4 + 0];
                v.y = acc[ai][jj * 4 + 1];
                v.z = acc[ai][jj * 4 + 2];
                v.w = acc[ai][jj * 4 + 3];
                if (bias) {
                    const float* b4 = bias + gn;
                    v.x += b4[0]; v.y += b4[1]; v.z += b4[2]; v.w += b4[3];
                }
                if (reluOut) {
                    v.x = fmaxf(v.x, 0.f); v.y = fmaxf(v.y, 0.f);
                    v.z = fmaxf(v.z, 0.f); v.w = fmaxf(v.w, 0.f);
                }
                *reinterpret_cast<float4*>(C + (size_t)gm * N + gn) = v;
            }
        }
    }
}

// ---------------- segment pool (sum + max), values >= 0 -----------
__global__ void segpool_kernel(const float* __restrict__ in,
                               const int* __restrict__ gatherIdx,
                               const int* __restrict__ seg,
                               int M, int F,
                               float* __restrict__ outSum,
                               float* __restrict__ outMax,
                               int ldOut, int nodesPerBlock) {
    int f = threadIdx.x;
    int n0 = blockIdx.x * nodesPerBlock;
    int n1 = n0 + nodesPerBlock;
    if (n1 > M) n1 = M;
    if (n0 >= n1) return;
    int cur = seg[n0];
    float s = 0.f, mx = 0.f;
    for (int n = n0; n < n1; n++) {
        int sg = seg[n];
        if (sg != cur) {
            atomicAdd(&outSum[cur * ldOut + f], s);
            atomicMax((int*)&outMax[cur * ldOut + f], __float_as_int(mx));
            s = 0.f; mx = 0.f; cur = sg;
        }
        int rowi = gatherIdx ? gatherIdx[n] : n;
        float v = in[(size_t)rowi * F + f];
        s += v;
        mx = fmaxf(mx, v);
    }
    atomicAdd(&outSum[cur * ldOut + f], s);
    atomicMax((int*)&outMax[cur * ldOut + f], __float_as_int(mx));
}

// ---------------- head ----------------
__global__ void head_kernel(const float* __restrict__ z,
                            const float* __restrict__ gamma,
                            const float* __restrict__ beta,
                            const float* __restrict__ mean,
                            const float* __restrict__ var,
                            const float* __restrict__ W1,
                            const float* __restrict__ b1,
                            const float* __restrict__ W2,
                            const float* __restrict__ b2,
                            float* __restrict__ out) {
    __shared__ float zn[4 * HC];
    __shared__ float s1[HC];
    __shared__ float logits[16];
    int b = blockIdx.x;
    int t = threadIdx.x;
    for (int k = t; k < 4 * HC; k += 256) {
        float v = z[b * 4 * HC + k];
        zn[k] = (v - mean[k]) * rsqrtf(var[k] + 1e-5f) * gamma[k] + beta[k];
    }
    __syncthreads();
    float acc = b1[t];
    for (int k = 0; k < 4 * HC; k++) acc += zn[k] * W1[k * HC + t];
    s1[t] = fmaxf(acc, 0.f);
    __syncthreads();
    if (t < 10) {
        float a2 = b2[t];
        for (int k = 0; k < HC; k++) a2 += s1[k] * W2[k * 10 + t];
        logits[t] = a2;
    }
    __syncthreads();
    if (t == 0) {
        float mx = logits[0];
        for (int c = 1; c < 10; c++) mx = fmaxf(mx, logits[c]);
        float e[10], sum = 0.f;
        for (int c = 0; c < 10; c++) { e[c] = expf(logits[c] - mx); sum += e[c]; }
        float inv = 1.f / sum;
        for (int c = 0; c < 10; c++) out[b * 10 + c] = e[c] * inv;
    }
}

// ---------------- orchestration ----------------
static inline int ceil_div(int a, int b) { return (a + b - 1) / b; }

extern "C" void kernel_launch(void* const* d_in, const int* in_sizes, int n_in,
                              void* d_out, int out_size) {
    const float* x      = (const float*)d_in[0];
    const int*   ei0    = (const int*)d_in[1];
    const float* ew0    = (const float*)d_in[2];
    const int*   batch0 = (const int*)d_in[3];
    const int*   cover  = (const int*)d_in[4];
    const int*   ei1    = (const int*)d_in[5];
    const float* ew1    = (const float*)d_in[6];
    const int*   batch1 = (const int*)d_in[7];
    const float* W_in0  = (const float*)d_in[8];
    const float* b_in0  = (const float*)d_in[9];
    const float* W_in1  = (const float*)d_in[10];
    const float* b_in1  = (const float*)d_in[11];
    const float* W_jk_in= (const float*)d_in[12];
    const float* b_jk_in= (const float*)d_in[13];
    const float* W_b0   = (const float*)d_in[14];
    const float* b_b0   = (const float*)d_in[15];
    const float* W_b1   = (const float*)d_in[16];
    const float* b_b1   = (const float*)d_in[17];
    const float* W_jk_b = (const float*)d_in[18];
    const float* b_jk_b = (const float*)d_in[19];
    const float* bn_g   = (const float*)d_in[20];
    const float* bn_b   = (const float*)d_in[21];
    const float* bn_m   = (const float*)d_in[22];
    const float* bn_v   = (const float*)d_in[23];
    const float* W_lin1 = (const float*)d_in[24];
    const float* b_lin1 = (const float*)d_in[25];
    const float* W_lin2 = (const float*)d_in[26];
    const float* b_lin2 = (const float*)d_in[27];
    float* out = (float*)d_out;

    const int N0 = in_sizes[3];
    const int E0 = in_sizes[2];
    const int N1 = in_sizes[7];
    const int E1 = in_sizes[6];
    const int H = HC;

    const int* row0 = ei0;
    const int* col0 = ei0 + E0;
    const int* nodeC = cover;
    const int* clusC = cover + N0;
    const int* row1 = ei1;
    const int* col1 = ei1 + E1;

    float *xw, *x1, *x2, *h, *dinv0, *h1cat, *yw, *y1, *y2, *hb, *dinv1, *z;
    cudaGetSymbolAddress((void**)&xw, g_xw);
    cudaGetSymbolAddress((void**)&x1, g_x1);
    cudaGetSymbolAddress((void**)&x2, g_x2);
    cudaGetSymbolAddress((void**)&h,  g_h);
    cudaGetSymbolAddress((void**)&dinv0, g_dinv0);
    cudaGetSymbolAddress((void**)&h1cat, g_h1cat);
    cudaGetSymbolAddress((void**)&yw, g_yw);
    cudaGetSymbolAddress((void**)&y1, g_y1);
    cudaGetSymbolAddress((void**)&y2, g_y2);
    cudaGetSymbolAddress((void**)&hb, g_hb);
    cudaGetSymbolAddress((void**)&dinv1, g_dinv1);
    cudaGetSymbolAddress((void**)&z,  g_z);

    dim3 gemmBlk(256);
    dim3 g0(H / TBN, ceil_div(N0, TBM));
    dim3 g1(H / TBN, ceil_div(N1, TBM));

    // ncu (-s 5 -c 1 incl. 2 harness launches) profiles MY 4th launch -> big GEMM there.
    fill_kernel<<<ceil_div(N0, 256), 256>>>(dinv0, N0, 1.f);                 // 1
    deg_accum_kernel<<<ceil_div(E0, 256), 256>>>(col0, ew0, dinv0, E0);      // 2
    finalize_dinv_kernel<<<ceil_div(N0, 256), 256>>>(dinv0, N0);             // 3

    // ---- level 0: GCN 1 ----
    gemm128_kernel<<<g0, gemmBlk>>>(x, x, FC, FC, W_in0, NULL, xw, N0, H, 0, 0);  // 4 (profiled)
    self_init_kernel<<<ceil_div(N0 * H, 256), 256>>>(x1, xw, dinv0, b_in0, N0, H);
    gcn_scatter_kernel<<<ceil_div(E0, 8), 256>>>(xw, row0, col0, ew0, dinv0, x1, E0, H, 8);

    // level-1 dinv + zero-fills (independent)
    fill_kernel<<<ceil_div(N1, 256), 256>>>(dinv1, N1, 1.f);
    deg_accum_kernel<<<ceil_div(E1, 256), 256>>>(col1, ew1, dinv1, E1);
    finalize_dinv_kernel<<<ceil_div(N1, 256), 256>>>(dinv1, N1);
    fill_kernel<<<ceil_div(BC * 4 * H, 256), 256>>>(z, BC * 4 * H, 0.f);
    fill_kernel<<<ceil_div(N1 * 2 * H, 256), 256>>>(h1cat, N1 * 2 * H, 0.f);

    // ---- level 0: GCN 2 ----
    gemm128_kernel<<<g0, gemmBlk>>>(x1, x1, H, H, W_in1, NULL, xw, N0, H, 1, 0);
    self_init_kernel<<<ceil_div(N0 * H, 256), 256>>>(x2, xw, dinv0, b_in1, N0, H);
    gcn_scatter_kernel<<<ceil_div(E0, 8), 256>>>(xw, row0, col0, ew0, dinv0, x2, E0, H, 8);

    // ---- level 0: JK cat + linear + relu ----
    gemm128_kernel<<<g0, gemmBlk>>>(x1, x2, H, 2 * H, W_jk_in, b_jk_in, h, N0, H, 1, 1);

    // ---- pools ----
    segpool_kernel<<<ceil_div(N0, 128), 256>>>(h, NULL, batch0, N0, H,
                                               z + 0, z + H, 4 * H, 128);
    segpool_kernel<<<ceil_div(N0, 128), 256>>>(h, nodeC, clusC, N0, H,
                                               h1cat + 0, h1cat + H, 2 * H, 128);

    // ---- level 1: GCN 1 ----
    gemm128_kernel<<<g1, gemmBlk>>>(h1cat, h1cat, 2 * H, 2 * H, W_b0, NULL, yw, N1, H, 0, 0);
    self_init_kernel<<<ceil_div(N1 * H, 256), 256>>>(y1, yw, dinv1, b_b0, N1, H);
    gcn_scatter_kernel<<<ceil_div(E1, 8), 256>>>(yw, row1, col1, ew1, dinv1, y1, E1, H, 8);

    // ---- level 1: GCN 2 ----
    gemm128_kernel<<<g1, gemmBlk>>>(y1, y1, H, H, W_b1, NULL, yw, N1, H, 1, 0);
    self_init_kernel<<<ceil_div(N1 * H, 256), 256>>>(y2, yw, dinv1, b_b1, N1, H);
    gcn_scatter_kernel<<<ceil_div(E1, 8), 256>>>(yw, row1, col1, ew1, dinv1, y2, E1, H, 8);

    // ---- level 1: JK ----
    gemm128_kernel<<<g1, gemmBlk>>>(y1, y2, H, 2 * H, W_jk_b, b_jk_b, hb, N1, H, 1, 1);

    // ---- level-1 batch pool ----
    segpool_kernel<<<ceil_div(N1, 128), 256>>>(hb, NULL, batch1, N1, H,
                                               z + 2 * H, z + 3 * H, 4 * H, 128);

    // ---- head ----
    head_kernel<<<BC, 256>>>(z, bn_g, bn_b, bn_m, bn_v,
                             W_lin1, b_lin1, W_lin2, b_lin2, out);
}

// round 4
// speedup vs baseline: 1.4538x; 1.1407x over previous
#include <cuda_runtime.h>
#include <math.h>

#define N0C 50000
#define E0C 800000
#define N1C 10000
#define E1C 160000
#define FC  128
#define HC  256
#define BC  64

// ---------------- static scratch ----------------
__device__ float g_xw [N0C * HC];
__device__ float g_x1 [N0C * HC];
__device__ float g_x2 [N0C * HC];
__device__ float g_h  [N0C * HC];
__device__ float g_dinv0[N0C];

__device__ float g_h1cat[N1C * 2 * HC];
__device__ float g_yw [N1C * HC];
__device__ float g_y1 [N1C * HC];
__device__ float g_y2 [N1C * HC];
__device__ float g_hb [N1C * HC];
__device__ float g_dinv1[N1C];

__device__ float g_z [BC * 4 * HC];

// ---------------- utility kernels ----------------
__global__ void fill_kernel(float* p, int n, float v) {
    int i = blockIdx.x * blockDim.x + threadIdx.x;
    if (i < n) p[i] = v;
}

__global__ void deg_accum_kernel(const int* __restrict__ col,
                                 const float* __restrict__ ew,
                                 float* __restrict__ deg, int E) {
    int e = blockIdx.x * blockDim.x + threadIdx.x;
    if (e < E) atomicAdd(&deg[col[e]], ew[e]);
}

__global__ void finalize_dinv_kernel(float* deg, int n) {
    int i = blockIdx.x * blockDim.x + threadIdx.x;
    if (i < n) {
        float d = deg[i];
        deg[i] = (d > 0.f) ? rsqrtf(d) : 0.f;
    }
}

// Edge scatter with vector reductions: out[col,:] += coef * xw[row,:]
// 256 threads = 64 float4 lanes x 4 edge slots. One REDG.128 per lane per edge.
__global__ void gcn_scatter_red4(const float* __restrict__ xw,
                                 const int* __restrict__ row,
                                 const int* __restrict__ col,
                                 const float* __restrict__ ew,
                                 const float* __restrict__ dinv,
                                 float* __restrict__ out,
                                 int E, int edgesPerBlock) {
    int f4 = threadIdx.x & 63;   // feature group: floats [f4*4, f4*4+3]
    int es = threadIdx.x >> 6;   // edge slot 0..3
    int e0 = blockIdx.x * edgesPerBlock;
    int e1 = e0 + edgesPerBlock;
    if (e1 > E) e1 = E;
    for (int e = e0 + es; e < e1; e += 4) {
        int r = row[e], c = col[e];
        float coef = dinv[r] * ew[e] * dinv[c];
        float4 v = *reinterpret_cast<const float4*>(xw + (size_t)r * HC + f4 * 4);
        float* dst = out + (size_t)c * HC + f4 * 4;
        asm volatile("red.global.add.v4.f32 [%0], {%1, %2, %3, %4};"
                     :: "l"(dst),
                        "f"(coef * v.x), "f"(coef * v.y),
                        "f"(coef * v.z), "f"(coef * v.w)
                     : "memory");
    }
}

// ---------------- 128x128 BK=8 double-buffered SGEMM ----------------
// C  = raw A@W           (when C2 != NULL; used as scatter gather source)
// C2 = bias + dinv^2 * (A@W)   (self-loop init, when C2 != NULL)
// else C = act(A@W + bias) as before.
#define TBM 128
#define TBN 128
#define TBK 8

__global__ __launch_bounds__(256)
void gemm128_kernel(const float* __restrict__ A1,
                    const float* __restrict__ A2,
                    int K1, int K,
                    const float* __restrict__ W,
                    const float* __restrict__ bias,
                    float* __restrict__ C,
                    float* __restrict__ C2,
                    const float* __restrict__ dinv,
                    int M, int N,
                    int reluIn, int reluOut) {
    __shared__ __align__(16) float As[2][TBK][TBM];
    __shared__ __align__(16) float Ws[2][TBK][TBN];

    const int bm = blockIdx.y * TBM;
    const int bn = blockIdx.x * TBN;
    const int tid = threadIdx.x;
    const int tx = tid & 15;       // N dir
    const int ty = tid >> 4;       // M dir
    const int K2 = K - K1;

    const int arow = tid >> 1;
    const int akq  = tid & 1;
    const int wk  = tid >> 5;
    const int wn4 = tid & 31;

    float acc[8][8];
#pragma unroll
    for (int i = 0; i < 8; i++)
#pragma unroll
        for (int j = 0; j < 8; j++) acc[i][j] = 0.f;

    const int nt = K / TBK;

    // ---- load tile 0 ----
    {
        int gm = bm + arow;
        float4 va = make_float4(0.f, 0.f, 0.f, 0.f);
        if (gm < M) {
            const float* src = (0 < K1) ? (A1 + (size_t)gm * K1) : (A2 + (size_t)gm * K2 - K1);
            va = *reinterpret_cast<const float4*>(src + akq * 4);
        }
        if (reluIn) {
            va.x = fmaxf(va.x, 0.f); va.y = fmaxf(va.y, 0.f);
            va.z = fmaxf(va.z, 0.f); va.w = fmaxf(va.w, 0.f);
        }
        As[0][akq * 4 + 0][arow] = va.x;
        As[0][akq * 4 + 1][arow] = va.y;
        As[0][akq * 4 + 2][arow] = va.z;
        As[0][akq * 4 + 3][arow] = va.w;
        float4 vw = *reinterpret_cast<const float4*>(W + (size_t)wk * N + bn + wn4 * 4);
        *reinterpret_cast<float4*>(&Ws[0][wk][wn4 * 4]) = vw;
    }
    __syncthreads();

    int cur = 0;
    for (int t = 0; t < nt; t++) {
        float4 pa, pw;
        const bool more = (t + 1 < nt);
        if (more) {
            const int gk0 = (t + 1) * TBK;
            int gm = bm + arow;
            pa = make_float4(0.f, 0.f, 0.f, 0.f);
            if (gm < M) {
                const float* src = (gk0 < K1) ? (A1 + (size_t)gm * K1 + gk0)
                                              : (A2 + (size_t)gm * K2 + (gk0 - K1));
                pa = *reinterpret_cast<const float4*>(src + akq * 4);
            }
            if (reluIn) {
                pa.x = fmaxf(pa.x, 0.f); pa.y = fmaxf(pa.y, 0.f);
                pa.z = fmaxf(pa.z, 0.f); pa.w = fmaxf(pa.w, 0.f);
            }
            pw = *reinterpret_cast<const float4*>(W + (size_t)(gk0 + wk) * N + bn + wn4 * 4);
        }

#pragma unroll
        for (int k = 0; k < TBK; k++) {
            float4 a0 = *reinterpret_cast<const float4*>(&As[cur][k][ty * 4]);
            float4 a1 = *reinterpret_cast<const float4*>(&As[cur][k][64 + ty * 4]);
            float4 w0 = *reinterpret_cast<const float4*>(&Ws[cur][k][tx * 4]);
            float4 w1 = *reinterpret_cast<const float4*>(&Ws[cur][k][64 + tx * 4]);
            float a[8] = {a0.x, a0.y, a0.z, a0.w, a1.x, a1.y, a1.z, a1.w};
            float w[8] = {w0.x, w0.y, w0.z, w0.w, w1.x, w1.y, w1.z, w1.w};
#pragma unroll
            for (int i = 0; i < 8; i++)
#pragma unroll
                for (int j = 0; j < 8; j++)
                    acc[i][j] += a[i] * w[j];
        }

        if (more) {
            int nxt = cur ^ 1;
            As[nxt][akq * 4 + 0][arow] = pa.x;
            As[nxt][akq * 4 + 1][arow] = pa.y;
            As[nxt][akq * 4 + 2][arow] = pa.z;
            As[nxt][akq * 4 + 3][arow] = pa.w;
            *reinterpret_cast<float4*>(&Ws[nxt][wk][wn4 * 4]) = pw;
            __syncthreads();
            cur = nxt;
        }
    }

    // epilogue
#pragma unroll
    for (int g = 0; g < 2; g++) {
#pragma unroll
        for (int i = 0; i < 4; i++) {
            int gm = bm + g * 64 + ty * 4 + i;
            if (gm >= M) continue;
            int ai = g * 4 + i;
            float dd = 0.f;
            if (C2) {
                float dv = dinv[gm];
                dd = dv * dv;
            }
#pragma unroll
            for (int jj = 0; jj < 2; jj++) {
                int gn = bn + jj * 64 + tx * 4;
                float4 v;
                v.x = acc[ai][jj * 4 + 0];
                v.y = acc[ai][jj * 4 + 1];
                v.z = acc[ai][jj * 4 + 2];
                v.w = acc[ai][jj * 4 + 3];
                if (C2) {
                    // C gets raw product (scatter gather source)
                    *reinterpret_cast<float4*>(C + (size_t)gm * N + gn) = v;
                    const float* b4 = bias + gn;
                    float4 v2;
                    v2.x = b4[0] + dd * v.x;
                    v2.y = b4[1] + dd * v.y;
                    v2.z = b4[2] + dd * v.z;
                    v2.w = b4[3] + dd * v.w;
                    *reinterpret_cast<float4*>(C2 + (size_t)gm * N + gn) = v2;
                } else {
                    if (bias) {
                        const float* b4 = bias + gn;
                        v.x += b4[0]; v.y += b4[1]; v.z += b4[2]; v.w += b4[3];
                    }
                    if (reluOut) {
                        v.x = fmaxf(v.x, 0.f); v.y = fmaxf(v.y, 0.f);
                        v.z = fmaxf(v.z, 0.f); v.w = fmaxf(v.w, 0.f);
                    }
                    *reinterpret_cast<float4*>(C + (size_t)gm * N + gn) = v;
                }
            }
        }
    }
}

// ---------------- segment pool (sum + max), values >= 0 -----------
__global__ void segpool_kernel(const float* __restrict__ in,
                               const int* __restrict__ gatherIdx,
                               const int* __restrict__ seg,
                               int M, int F,
                               float* __restrict__ outSum,
                               float* __restrict__ outMax,
                               int ldOut, int nodesPerBlock) {
    int f = threadIdx.x;
    int n0 = blockIdx.x * nodesPerBlock;
    int n1 = n0 + nodesPerBlock;
    if (n1 > M) n1 = M;
    if (n0 >= n1) return;
    int cur = seg[n0];
    float s = 0.f, mx = 0.f;
    for (int n = n0; n < n1; n++) {
        int sg = seg[n];
        if (sg != cur) {
            atomicAdd(&outSum[cur * ldOut + f], s);
            atomicMax((int*)&outMax[cur * ldOut + f], __float_as_int(mx));
            s = 0.f; mx = 0.f; cur = sg;
        }
        int rowi = gatherIdx ? gatherIdx[n] : n;
        float v = in[(size_t)rowi * F + f];
        s += v;
        mx = fmaxf(mx, v);
    }
    atomicAdd(&outSum[cur * ldOut + f], s);
    atomicMax((int*)&outMax[cur * ldOut + f], __float_as_int(mx));
}

// ---------------- head ----------------
__global__ void head_kernel(const float* __restrict__ z,
                            const float* __restrict__ gamma,
                            const float* __restrict__ beta,
                            const float* __restrict__ mean,
                            const float* __restrict__ var,
                            const float* __restrict__ W1,
                            const float* __restrict__ b1,
                            const float* __restrict__ W2,
                            const float* __restrict__ b2,
                            float* __restrict__ out) {
    __shared__ float zn[4 * HC];
    __shared__ float s1[HC];
    __shared__ float logits[16];
    int b = blockIdx.x;
    int t = threadIdx.x;
    for (int k = t; k < 4 * HC; k += 256) {
        float v = z[b * 4 * HC + k];
        zn[k] = (v - mean[k]) * rsqrtf(var[k] + 1e-5f) * gamma[k] + beta[k];
    }
    __syncthreads();
    float acc = b1[t];
    for (int k = 0; k < 4 * HC; k++) acc += zn[k] * W1[k * HC + t];
    s1[t] = fmaxf(acc, 0.f);
    __syncthreads();
    if (t < 10) {
        float a2 = b2[t];
        for (int k = 0; k < HC; k++) a2 += s1[k] * W2[k * 10 + t];
        logits[t] = a2;
    }
    __syncthreads();
    if (t == 0) {
        float mx = logits[0];
        for (int c = 1; c < 10; c++) mx = fmaxf(mx, logits[c]);
        float e[10], sum = 0.f;
        for (int c = 0; c < 10; c++) { e[c] = expf(logits[c] - mx); sum += e[c]; }
        float inv = 1.f / sum;
        for (int c = 0; c < 10; c++) out[b * 10 + c] = e[c] * inv;
    }
}

// ---------------- orchestration ----------------
static inline int ceil_div(int a, int b) { return (a + b - 1) / b; }

extern "C" void kernel_launch(void* const* d_in, const int* in_sizes, int n_in,
                              void* d_out, int out_size) {
    const float* x      = (const float*)d_in[0];
    const int*   ei0    = (const int*)d_in[1];
    const float* ew0    = (const float*)d_in[2];
    const int*   batch0 = (const int*)d_in[3];
    const int*   cover  = (const int*)d_in[4];
    const int*   ei1    = (const int*)d_in[5];
    const float* ew1    = (const float*)d_in[6];
    const int*   batch1 = (const int*)d_in[7];
    const float* W_in0  = (const float*)d_in[8];
    const float* b_in0  = (const float*)d_in[9];
    const float* W_in1  = (const float*)d_in[10];
    const float* b_in1  = (const float*)d_in[11];
    const float* W_jk_in= (const float*)d_in[12];
    const float* b_jk_in= (const float*)d_in[13];
    const float* W_b0   = (const float*)d_in[14];
    const float* b_b0   = (const float*)d_in[15];
    const float* W_b1   = (const float*)d_in[16];
    const float* b_b1   = (const float*)d_in[17];
    const float* W_jk_b = (const float*)d_in[18];
    const float* b_jk_b = (const float*)d_in[19];
    const float* bn_g   = (const float*)d_in[20];
    const float* bn_b   = (const float*)d_in[21];
    const float* bn_m   = (const float*)d_in[22];
    const float* bn_v   = (const float*)d_in[23];
    const float* W_lin1 = (const float*)d_in[24];
    const float* b_lin1 = (const float*)d_in[25];
    const float* W_lin2 = (const float*)d_in[26];
    const float* b_lin2 = (const float*)d_in[27];
    float* out = (float*)d_out;

    const int N0 = in_sizes[3];
    const int E0 = in_sizes[2];
    const int N1 = in_sizes[7];
    const int E1 = in_sizes[6];
    const int H = HC;

    const int* row0 = ei0;
    const int* col0 = ei0 + E0;
    const int* nodeC = cover;
    const int* clusC = cover + N0;
    const int* row1 = ei1;
    const int* col1 = ei1 + E1;

    float *xw, *x1, *x2, *h, *dinv0, *h1cat, *yw, *y1, *y2, *hb, *dinv1, *z;
    cudaGetSymbolAddress((void**)&xw, g_xw);
    cudaGetSymbolAddress((void**)&x1, g_x1);
    cudaGetSymbolAddress((void**)&x2, g_x2);
    cudaGetSymbolAddress((void**)&h,  g_h);
    cudaGetSymbolAddress((void**)&dinv0, g_dinv0);
    cudaGetSymbolAddress((void**)&h1cat, g_h1cat);
    cudaGetSymbolAddress((void**)&yw, g_yw);
    cudaGetSymbolAddress((void**)&y1, g_y1);
    cudaGetSymbolAddress((void**)&y2, g_y2);
    cudaGetSymbolAddress((void**)&hb, g_hb);
    cudaGetSymbolAddress((void**)&dinv1, g_dinv1);
    cudaGetSymbolAddress((void**)&z,  g_z);

    dim3 gemmBlk(256);
    dim3 g0(H / TBN, ceil_div(N0, TBM));
    dim3 g1(H / TBN, ceil_div(N1, TBM));

    // ncu (-s 5 -c 1 incl. 2 harness launches) profiles MY 4th launch (the big GEMM).
    fill_kernel<<<ceil_div(N0, 256), 256>>>(dinv0, N0, 1.f);                 // 1
    deg_accum_kernel<<<ceil_div(E0, 256), 256>>>(col0, ew0, dinv0, E0);      // 2
    finalize_dinv_kernel<<<ceil_div(N0, 256), 256>>>(dinv0, N0);             // 3

    // ---- level 0: GCN 1 (fused: xw=x@W, x1=b+dinv^2*xw) ----
    gemm128_kernel<<<g0, gemmBlk>>>(x, x, FC, FC, W_in0, b_in0, xw, x1, dinv0,
                                    N0, H, 0, 0);                            // 4 (profiled)
    gcn_scatter_red4<<<ceil_div(E0, 16), 256>>>(xw, row0, col0, ew0, dinv0, x1, E0, 16);

    // level-1 dinv + zero-fills (independent)
    fill_kernel<<<ceil_div(N1, 256), 256>>>(dinv1, N1, 1.f);
    deg_accum_kernel<<<ceil_div(E1, 256), 256>>>(col1, ew1, dinv1, E1);
    finalize_dinv_kernel<<<ceil_div(N1, 256), 256>>>(dinv1, N1);
    fill_kernel<<<ceil_div(BC * 4 * H, 256), 256>>>(z, BC * 4 * H, 0.f);
    fill_kernel<<<ceil_div(N1 * 2 * H, 256), 256>>>(h1cat, N1 * 2 * H, 0.f);

    // ---- level 0: GCN 2 ----
    gemm128_kernel<<<g0, gemmBlk>>>(x1, x1, H, H, W_in1, b_in1, xw, x2, dinv0,
                                    N0, H, 1, 0);
    gcn_scatter_red4<<<ceil_div(E0, 16), 256>>>(xw, row0, col0, ew0, dinv0, x2, E0, 16);

    // ---- level 0: JK cat + linear + relu ----
    gemm128_kernel<<<g0, gemmBlk>>>(x1, x2, H, 2 * H, W_jk_in, b_jk_in, h, NULL, NULL,
                                    N0, H, 1, 1);

    // ---- pools ----
    segpool_kernel<<<ceil_div(N0, 128), 256>>>(h, NULL, batch0, N0, H,
                                               z + 0, z + H, 4 * H, 128);
    segpool_kernel<<<ceil_div(N0, 128), 256>>>(h, nodeC, clusC, N0, H,
                                               h1cat + 0, h1cat + H, 2 * H, 128);

    // ---- level 1: GCN 1 ----
    gemm128_kernel<<<g1, gemmBlk>>>(h1cat, h1cat, 2 * H, 2 * H, W_b0, b_b0, yw, y1, dinv1,
                                    N1, H, 0, 0);
    gcn_scatter_red4<<<ceil_div(E1, 16), 256>>>(yw, row1, col1, ew1, dinv1, y1, E1, 16);

    // ---- level 1: GCN 2 ----
    gemm128_kernel<<<g1, gemmBlk>>>(y1, y1, H, H, W_b1, b_b1, yw, y2, dinv1,
                                    N1, H, 1, 0);
    gcn_scatter_red4<<<ceil_div(E1, 16), 256>>>(yw, row1, col1, ew1, dinv1, y2, E1, 16);

    // ---- level 1: JK ----
    gemm128_kernel<<<g1, gemmBlk>>>(y1, y2, H, 2 * H, W_jk_b, b_jk_b, hb, NULL, NULL,
                                    N1, H, 1, 1);

    // ---- level-1 batch pool ----
    segpool_kernel<<<ceil_div(N1, 128), 256>>>(hb, NULL, batch1, N1, H,
                                               z + 2 * H, z + 3 * H, 4 * H, 128);

    // ---- head ----
    head_kernel<<<BC, 256>>>(z, bn_g, bn_b, bn_m, bn_v,
                             W_lin1, b_lin1, W_lin2, b_lin2, out);
}